// round 11
// baseline (speedup 1.0000x reference)
#include <cuda_runtime.h>
#include <cstdint>

// Problem constants (fixed by reference setup_inputs)
#define Bn 16
#define Cn 128
#define TA 2048
#define TB 1024
#define Rn TA   // reference timeline = modality A
#define GC 8    // channels per gather thread

// Output layout (float32, flattened in return order)
#define OFF_ALIGNED 0
#define OFF_MASK    8388608
#define OFF_IDX     8454144
#define OFF_RATIO   8519680

// Integer copy of the nearest-index table (avoids float->int cvt in gather)
__device__ int d_idxi[32 * 2048];

// -----------------------------------------------------------------------------
// Kernel 1 (fused): per-block redundant compaction + binary search + ratio.
// Grid: 256 blocks of 256 threads. blockIdx.x -> (mb = m*16+b, chunk of 256 refs).
// -----------------------------------------------------------------------------
__global__ __launch_bounds__(256)
void align_kernel(const float* __restrict__ ta, const float* __restrict__ ma,  // A t,m [B,TA]
                  const float* __restrict__ tb, const float* __restrict__ mb_, // B t,m [B,TB]
                  float* __restrict__ mask_out,  // [2,B,R]
                  float* __restrict__ idx_out,   // [2,B,R]
                  float* __restrict__ ratio)     // [2,B]
{
    __shared__ float s_t[2048];
    __shared__ int   s_i[2048];
    __shared__ int   wtot[8], woff[8];
    __shared__ int   s_nvA;

    const int t     = threadIdx.x;
    const int chunk = blockIdx.x & 7;
    const int mb    = blockIdx.x >> 3;    // 0..31
    const int m     = mb >> 4;
    const int b     = mb & 15;
    const int S     = m ? TB : TA;

    const float* src_t = (m ? tb : ta) + (size_t)b * S;
    const float* src_m = (m ? mb_ : ma) + (size_t)b * S;

    // ---- order-preserving compaction into smem ----
    const int per  = S >> 8;              // 8 (A) or 4 (B)
    const int base = t * per;
    const int lane = t & 31, wid = t >> 5;

    float v_t[8];
    float v_m[8];
    #pragma unroll
    for (int i = 0; i < 8; i++) {
        if (i < per) {
            v_t[i] = src_t[base + i];
            v_m[i] = src_m[base + i];
        }
    }
    int cnt = 0;
    #pragma unroll
    for (int i = 0; i < 8; i++)
        if (i < per) cnt += (v_m[i] > 0.0f) ? 1 : 0;

    // block scan: warp shuffle scan + warp-total scan
    int inc = cnt;
    #pragma unroll
    for (int off = 1; off < 32; off <<= 1) {
        int v = __shfl_up_sync(0xffffffffu, inc, off);
        if (lane >= off) inc += v;
    }
    if (lane == 31) wtot[wid] = inc;
    __syncthreads();
    if (t < 8) {
        int v = wtot[t];
        int s = v;
        #pragma unroll
        for (int off = 1; off < 8; off <<= 1) {
            int u = __shfl_up_sync(0x000000ffu, s, off);
            if (t >= off) s += u;
        }
        woff[t] = s - v;                  // exclusive warp offset
    }
    __syncthreads();

    int pos = woff[wid] + inc - cnt;      // exclusive prefix for this thread
    #pragma unroll
    for (int i = 0; i < 8; i++) {
        if (i < per && v_m[i] > 0.0f) {
            s_t[pos] = v_t[i];
            s_i[pos] = base + i;
            pos++;
        }
    }
    const int nv = woff[7] + wtot[7];     // total valid count
    __syncthreads();

    // ---- binary search: 256 refs per block, one per thread ----
    const int r = chunk * 256 + t;
    const float rt = ta[(size_t)b * Rn + r];
    const bool ok = (ma[(size_t)b * Rn + r] > 0.0f) && (nv > 0);

    int idx = -1;
    if (ok) {
        int lo = 0, hi = nv;              // lower_bound: first s_t[pos] >= rt
        while (lo < hi) {
            int mid = (lo + hi) >> 1;
            if (s_t[mid] < rt) lo = mid + 1; else hi = mid;
        }
        int p;
        if (lo == 0) {
            p = 0;                                      // only right candidate
        } else if (lo == nv || (rt - s_t[lo - 1]) <= (s_t[lo] - rt)) {
            float tl = s_t[lo - 1];
            p = lo - 1;
            while (p > 0 && s_t[p - 1] == tl) p--;      // first duplicate
        } else {
            p = lo;                                     // lo is first occurrence
        }
        idx = s_i[p];
    }
    mask_out[(size_t)mb * Rn + r] = ok ? 1.0f : 0.0f;
    idx_out [(size_t)mb * Rn + r] = ok ? (float)idx : -1.0f;
    d_idxi  [(size_t)mb * Rn + r] = ok ? idx : -1;

    // ---- valid_ratio (chunk-0 blocks only) ----
    if (chunk == 0) {
        // ratio[m,b] = (nv>0 ? nvA : 0) / 2048, nvA = #valid in masks_a[b].
        if (m == 0) {
            if (t == 0)
                ratio[mb] = (nv > 0 ? (float)nv : 0.0f) * (1.0f / (float)Rn);
        } else {
            if (t == 0) s_nvA = 0;
            __syncthreads();
            const float* am = ma + (size_t)b * TA;
            int c2 = 0;
            #pragma unroll
            for (int i = 0; i < 8; i++)
                c2 += (am[t * 8 + i] > 0.0f) ? 1 : 0;
            #pragma unroll
            for (int off = 16; off > 0; off >>= 1)
                c2 += __shfl_down_sync(0xffffffffu, c2, off);
            if (lane == 0) atomicAdd(&s_nvA, c2);
            __syncthreads();
            if (t == 0)
                ratio[mb] = (nv > 0 ? (float)s_nvA : 0.0f) * (1.0f / (float)Rn);
        }
    }
}

// -----------------------------------------------------------------------------
// Kernel 2: gather, scalar-r lane mapping. Lane t handles r = rchunk*256 + t
// for GC=8 channels: warp gather addresses vrow[idx[r..r+31]] are near-
// monotone (1-2 cache lines per warp load), stores are 128B-coalesced.
// One idx load amortized over 8 channels; 8 independent gathers in flight.
// grid: mb(32) x ctile(16) x rchunk(8) = 4096 blocks of 256 threads.
// -----------------------------------------------------------------------------
__global__ __launch_bounds__(256)
void gather_kernel(const float* __restrict__ vals_a,  // [B,C,TA]
                   const float* __restrict__ vals_b,  // [B,C,TB]
                   float* __restrict__ out)           // [2,B,C,R]
{
    const int bid    = blockIdx.x;
    const int rchunk = bid & 7;
    const int ctile  = (bid >> 3) & 15;
    const int mb     = bid >> 7;          // 0..31
    const int m      = mb >> 4;
    const int b      = mb & 15;
    const int S      = m ? TB : TA;
    const float* vals = m ? vals_b : vals_a;

    const int r = rchunk * 256 + threadIdx.x;   // 0..2047

    const int idx = __ldg(d_idxi + (size_t)mb * Rn + r);
    const bool ok = idx >= 0;
    const int  ix = ok ? idx : 0;               // safe address, masked on use

    const float* vbase = vals + ((size_t)b * Cn + ctile * GC) * S + ix;
    float*       obase = out  + ((size_t)mb * Cn + ctile * GC) * Rn + r;

    float v[GC];
    #pragma unroll
    for (int c = 0; c < GC; c++)                // 8 independent gathers (MLP)
        v[c] = __ldg(vbase + (size_t)c * S);
    #pragma unroll
    for (int c = 0; c < GC; c++)
        obase[(size_t)c * Rn] = ok ? v[c] : 0.0f;
}

extern "C" void kernel_launch(void* const* d_in, const int* in_sizes, int n_in,
                              void* d_out, int out_size)
{
    const float* values_a     = (const float*)d_in[0];
    const float* timestamps_a = (const float*)d_in[1];
    const float* masks_a      = (const float*)d_in[2];
    const float* values_b     = (const float*)d_in[3];
    const float* timestamps_b = (const float*)d_in[4];
    const float* masks_b      = (const float*)d_in[5];
    float* out = (float*)d_out;

    float* aligned = out + OFF_ALIGNED;
    float* maskout = out + OFF_MASK;   // [2,B,R]
    float* idxout  = out + OFF_IDX;    // [2,B,R]
    float* ratio   = out + OFF_RATIO;  // [2,B]

    // Phase 1: fused compaction + search + ratio (256 blocks)
    align_kernel<<<256, 256>>>(timestamps_a, masks_a, timestamps_b, masks_b,
                               maskout, idxout, ratio);

    // Phase 2: gather -> aligned [2,B,C,R]
    gather_kernel<<<4096, 256>>>(values_a, values_b, aligned);

    (void)in_sizes; (void)n_in; (void)out_size;
}